// round 5
// baseline (speedup 1.0000x reference)
#include <cuda_runtime.h>
#include <cuda_bf16.h>

// out[b,t,v] = sum_d x[b,t,d,v] * w[d] + bias
// x: (B=2, T=512, D=8, V=32000) fp32 ; w: (8,) ; b: (1,)
// v3: persistent one-wave grid-stride kernel. 1184 CTAs (148 SMs x 8),
// each thread walks float4 output slots; 8 independent LDG.128 per slot,
// cross-iteration overlap via unroll-by-2. No wave transitions, no tail.

#define BT     1024          // B*T
#define DEPTH  8
#define V      32000
#define V4     (V / 4)       // 8000 float4 per (b,t,d) row
#define NOUT   (BT * V4)     // 8,192,000 float4 outputs
#define NBLK   1184          // 148 SMs * 8 resident CTAs
#define NTHR   256

__global__ __launch_bounds__(NTHR) void tokentree_kernel(
    const float4* __restrict__ x,   // (BT, DEPTH, V4)
    const float*  __restrict__ w,   // (DEPTH,)
    const float*  __restrict__ bias,// (1,)
    float4*       __restrict__ out) // (BT, V4)
{
    // Weights + bias: L1-resident after first access.
    float wr[DEPTH];
#pragma unroll
    for (int d = 0; d < DEPTH; d++) wr[d] = __ldg(&w[d]);
    const float b0 = __ldg(&bias[0]);

    const int stride = NBLK * NTHR;           // 303104
    int i = blockIdx.x * NTHR + threadIdx.x;

#pragma unroll 2
    for (; i < NOUT; i += stride) {
        const int bt = i / V4;                // mul-shift, cheap
        const int v4 = i - bt * V4;
        const float4* xp = x + (size_t)bt * (DEPTH * V4) + v4;

        // 8 independent coalesced 128B loads (per-warp: 32x16B contiguous).
        float4 x0 = __ldg(xp + 0 * V4);
        float4 x1 = __ldg(xp + 1 * V4);
        float4 x2 = __ldg(xp + 2 * V4);
        float4 x3 = __ldg(xp + 3 * V4);
        float4 x4 = __ldg(xp + 4 * V4);
        float4 x5 = __ldg(xp + 5 * V4);
        float4 x6 = __ldg(xp + 6 * V4);
        float4 x7 = __ldg(xp + 7 * V4);

        float4 acc;
        acc.x = b0; acc.y = b0; acc.z = b0; acc.w = b0;

        acc.x = fmaf(wr[0], x0.x, acc.x); acc.y = fmaf(wr[0], x0.y, acc.y);
        acc.z = fmaf(wr[0], x0.z, acc.z); acc.w = fmaf(wr[0], x0.w, acc.w);
        acc.x = fmaf(wr[1], x1.x, acc.x); acc.y = fmaf(wr[1], x1.y, acc.y);
        acc.z = fmaf(wr[1], x1.z, acc.z); acc.w = fmaf(wr[1], x1.w, acc.w);
        acc.x = fmaf(wr[2], x2.x, acc.x); acc.y = fmaf(wr[2], x2.y, acc.y);
        acc.z = fmaf(wr[2], x2.z, acc.z); acc.w = fmaf(wr[2], x2.w, acc.w);
        acc.x = fmaf(wr[3], x3.x, acc.x); acc.y = fmaf(wr[3], x3.y, acc.y);
        acc.z = fmaf(wr[3], x3.z, acc.z); acc.w = fmaf(wr[3], x3.w, acc.w);
        acc.x = fmaf(wr[4], x4.x, acc.x); acc.y = fmaf(wr[4], x4.y, acc.y);
        acc.z = fmaf(wr[4], x4.z, acc.z); acc.w = fmaf(wr[4], x4.w, acc.w);
        acc.x = fmaf(wr[5], x5.x, acc.x); acc.y = fmaf(wr[5], x5.y, acc.y);
        acc.z = fmaf(wr[5], x5.z, acc.z); acc.w = fmaf(wr[5], x5.w, acc.w);
        acc.x = fmaf(wr[6], x6.x, acc.x); acc.y = fmaf(wr[6], x6.y, acc.y);
        acc.z = fmaf(wr[6], x6.z, acc.z); acc.w = fmaf(wr[6], x6.w, acc.w);
        acc.x = fmaf(wr[7], x7.x, acc.x); acc.y = fmaf(wr[7], x7.y, acc.y);
        acc.z = fmaf(wr[7], x7.z, acc.z); acc.w = fmaf(wr[7], x7.w, acc.w);

        out[i] = acc;
    }
}

extern "C" void kernel_launch(void* const* d_in, const int* in_sizes, int n_in,
                              void* d_out, int out_size) {
    const float4* x    = (const float4*)d_in[0];
    const float*  w    = (const float*)d_in[1];
    const float*  bias = (const float*)d_in[2];
    float4*       out  = (float4*)d_out;

    tokentree_kernel<<<NBLK, NTHR>>>(x, w, bias, out);
}

// round 6
// speedup vs baseline: 1.0698x; 1.0698x over previous
#include <cuda_runtime.h>
#include <cuda_bf16.h>

// out[b,t,v] = sum_d x[b,t,d,v] * w[d] + bias
// x: (B=2, T=512, D=8, V=32000) fp32 ; w: (8,) ; b: (1,)
// v4: v1 structure (1 float4 out per thread, 8 front-batched LDG.128),
// with L2-only streaming reads (__ldcg) and 512-thread blocks
// (4 CTAs/SM x 512 = 2048 thr, 32 regs -> exact RF fit).

#define BT    1024      // B*T
#define DEPTH 8
#define V     32000
#define V4    (V / 4)   // 8000 float4 per (b,t,d) row
#define NTHR  512

__global__ __launch_bounds__(NTHR) void tokentree_kernel(
    const float4* __restrict__ x,   // (BT, DEPTH, V4)
    const float*  __restrict__ w,   // (DEPTH,)
    const float*  __restrict__ bias,// (1,)
    float4*       __restrict__ out) // (BT, V4)
{
    const int v4 = blockIdx.x * NTHR + threadIdx.x;
    if (v4 >= V4) return;
    const int bt = blockIdx.y;

    // Weights + bias: tiny, cache-resident after first warp.
    float w0 = __ldg(&w[0]), w1 = __ldg(&w[1]), w2 = __ldg(&w[2]), w3 = __ldg(&w[3]);
    float w4 = __ldg(&w[4]), w5 = __ldg(&w[5]), w6 = __ldg(&w[6]), w7 = __ldg(&w[7]);
    float b0 = __ldg(&bias[0]);

    const float4* xp = x + (size_t)bt * DEPTH * V4 + v4;

    // 8 independent coalesced 128B-per-warp loads, L2-only (no L1 fill,
    // zero reuse), front-batched -> MLP=8 per thread.
    float4 x0 = __ldcg(xp + 0 * V4);
    float4 x1 = __ldcg(xp + 1 * V4);
    float4 x2 = __ldcg(xp + 2 * V4);
    float4 x3 = __ldcg(xp + 3 * V4);
    float4 x4 = __ldcg(xp + 4 * V4);
    float4 x5 = __ldcg(xp + 5 * V4);
    float4 x6 = __ldcg(xp + 6 * V4);
    float4 x7 = __ldcg(xp + 7 * V4);

    float4 acc;
    acc.x = b0; acc.y = b0; acc.z = b0; acc.w = b0;

    acc.x = fmaf(w0, x0.x, acc.x); acc.y = fmaf(w0, x0.y, acc.y);
    acc.z = fmaf(w0, x0.z, acc.z); acc.w = fmaf(w0, x0.w, acc.w);
    acc.x = fmaf(w1, x1.x, acc.x); acc.y = fmaf(w1, x1.y, acc.y);
    acc.z = fmaf(w1, x1.z, acc.z); acc.w = fmaf(w1, x1.w, acc.w);
    acc.x = fmaf(w2, x2.x, acc.x); acc.y = fmaf(w2, x2.y, acc.y);
    acc.z = fmaf(w2, x2.z, acc.z); acc.w = fmaf(w2, x2.w, acc.w);
    acc.x = fmaf(w3, x3.x, acc.x); acc.y = fmaf(w3, x3.y, acc.y);
    acc.z = fmaf(w3, x3.z, acc.z); acc.w = fmaf(w3, x3.w, acc.w);
    acc.x = fmaf(w4, x4.x, acc.x); acc.y = fmaf(w4, x4.y, acc.y);
    acc.z = fmaf(w4, x4.z, acc.z); acc.w = fmaf(w4, x4.w, acc.w);
    acc.x = fmaf(w5, x5.x, acc.x); acc.y = fmaf(w5, x5.y, acc.y);
    acc.z = fmaf(w5, x5.z, acc.z); acc.w = fmaf(w5, x5.w, acc.w);
    acc.x = fmaf(w6, x6.x, acc.x); acc.y = fmaf(w6, x6.y, acc.y);
    acc.z = fmaf(w6, x6.z, acc.z); acc.w = fmaf(w6, x6.w, acc.w);
    acc.x = fmaf(w7, x7.x, acc.x); acc.y = fmaf(w7, x7.y, acc.y);
    acc.z = fmaf(w7, x7.z, acc.z); acc.w = fmaf(w7, x7.w, acc.w);

    out[(size_t)bt * V4 + v4] = acc;
}

extern "C" void kernel_launch(void* const* d_in, const int* in_sizes, int n_in,
                              void* d_out, int out_size) {
    const float4* x    = (const float4*)d_in[0];
    const float*  w    = (const float*)d_in[1];
    const float*  bias = (const float*)d_in[2];
    float4*       out  = (float4*)d_out;

    dim3 block(NTHR);
    dim3 grid((V4 + NTHR - 1) / NTHR, BT);   // (16, 1024)
    tokentree_kernel<<<grid, block>>>(x, w, bias, out);
}